// round 15
// baseline (speedup 1.0000x reference)
#include <cuda_runtime.h>
#include <cuda_fp16.h>
#include <cstdint>

// Problem dims (fixed by the reference)
#define QN   512
#define CN   512
#define TNT  128
#define DIN  512
#define DHD  256
#define KCORR (TNT * DHD)   // 32768
#define MAXLAG 4
#define NLAG  9             // lags -4..4
#define MROWS (QN * TNT)    // 65536

// ---------------------------------------------------------------------------
// Scratch (static device globals; no allocation allowed)
// ---------------------------------------------------------------------------
__device__ __half g_Hha[MROWS * DHD];   // audio hidden fp16
__device__ __half g_Hhv[MROWS * DHD];   // video hidden fp16
__device__ __half g_Ahf[MROWS * DHD];   // audio features fp16  [Q, T*DH]
__device__ __half g_Phf[MROWS * DHD];   // projected video fp16 [C, T*DH]
__device__ float g_Wc[DHD * DHD];       // folded v_w2 @ W (fp32)
__device__ float g_bc[DHD];             // folded v_b2 @ W
// pre-converted, pre-transposed weights: [N][K], K contiguous (fp16)
__device__ __half g_W1ah[DHD * DIN];
__device__ __half g_W1vh[DHD * DIN];
__device__ __half g_W2ah[DHD * DHD];
__device__ __half g_Wcth[DHD * DHD];
__device__ float g_Sp[NLAG * QN * CN];  // per-lag scores (atomicAdd partials)

// ---------------------------------------------------------------------------
// Portable PTX helpers (valid on compute_103 virtual target)
// ---------------------------------------------------------------------------
__device__ __forceinline__ uint32_t smem_u32(const void* p) {
    uint32_t a;
    asm("{ .reg .u64 t; cvta.to.shared.u64 t, %1; cvt.u32.u64 %0, t; }"
        : "=r"(a) : "l"(p));
    return a;
}

#define CP_ASYNC_16(dst, src) \
    asm volatile("cp.async.ca.shared.global [%0], [%1], 16;" \
        :: "r"(dst), "l"(src) : "memory")
#define CP_ASYNC_CG_16(dst, src) \
    asm volatile("cp.async.cg.shared.global [%0], [%1], 16;" \
        :: "r"(dst), "l"(src) : "memory")
#define CP_ASYNC_COMMIT() asm volatile("cp.async.commit_group;" ::: "memory")
#define CP_ASYNC_WAIT_1() asm volatile("cp.async.wait_group 1;" ::: "memory")
#define CP_ASYNC_WAIT_0() asm volatile("cp.async.wait_group 0;" ::: "memory")

#define LDSM_X4(r, addr) \
    asm volatile("ldmatrix.sync.aligned.m8n8.x4.shared.b16 {%0,%1,%2,%3}, [%4];" \
        : "=r"((r)[0]), "=r"((r)[1]), "=r"((r)[2]), "=r"((r)[3]) : "r"(addr))

__device__ __forceinline__ void mma_f16(float* c, const uint32_t* a,
                                        const uint32_t* b) {
    asm volatile(
        "mma.sync.aligned.m16n8k16.row.col.f32.f16.f16.f32 "
        "{%0,%1,%2,%3}, {%4,%5,%6,%7}, {%8,%9}, {%0,%1,%2,%3};"
        : "+f"(c[0]), "+f"(c[1]), "+f"(c[2]), "+f"(c[3])
        : "r"(a[0]), "r"(a[1]), "r"(a[2]), "r"(a[3]), "r"(b[0]), "r"(b[1]));
}

// ---------------------------------------------------------------------------
// Prep: fold v_w2 @ W -> g_Wc, g_bc
// ---------------------------------------------------------------------------
__global__ void prep_w_kernel(const float* __restrict__ v_w2,
                              const float* __restrict__ v_b2,
                              const float* __restrict__ W) {
    int i = blockIdx.x;
    int j = threadIdx.x;
    float acc = 0.f;
    #pragma unroll 8
    for (int k = 0; k < DHD; ++k)
        acc += v_w2[i * DHD + k] * W[k * DHD + j];
    g_Wc[i * DHD + j] = acc;
    if (i == 0) {
        float accb = 0.f;
        #pragma unroll 8
        for (int k = 0; k < DHD; ++k)
            accb += v_b2[k] * W[k * DHD + j];
        g_bc[j] = accb;
    }
}

// Prep: batched transpose+convert fp32 [K,256] -> fp16 [256][K] for 4 arrays,
// plus reset of g_Sp (blockIdx.y == 4).
__global__ void convt_all_kernel(const float* __restrict__ s0, __half* d0, int K0,
                                 const float* __restrict__ s1, __half* d1, int K1,
                                 const float* __restrict__ s2, __half* d2, int K2,
                                 const float* __restrict__ s3, __half* d3, int K3) {
    int which = blockIdx.y;
    if (which == 4) {   // reset g_Sp to 0
        int idx = blockIdx.x * blockDim.x + threadIdx.x;
        for (; idx < NLAG * QN * CN; idx += gridDim.x * blockDim.x)
            g_Sp[idx] = 0.f;
        return;
    }
    const float* in; __half* oh; int K;
    if (which == 0)      { in = s0; oh = d0; K = K0; }
    else if (which == 1) { in = s1; oh = d1; K = K1; }
    else if (which == 2) { in = s2; oh = d2; K = K2; }
    else                 { in = s3; oh = d3; K = K3; }
    int n = blockIdx.x;
    for (int k = threadIdx.x; k < K; k += blockDim.x)
        oh[(size_t)n * K + k] = __float2half_rn(in[(size_t)k * DHD + n]);
}

// ---------------------------------------------------------------------------
// MLP tiling constants (2 tiles: A, B)
// ---------------------------------------------------------------------------
#define BKC     32                  // K elems per chunk (MLP)
#define ROWB    80                  // padded row stride bytes (64 data + 16)
#define TILE_PB (128 * ROWB)        // 10240
#define BUF_PB  (2 * TILE_PB)       // A, B = 20480
#define HMMA_SMEM (2 * BUF_PB)      // 40960

extern __shared__ char dsm[];

// ---------------------------------------------------------------------------
// MLP GEMM on HMMA, pure fp16, batched over audio/video via blockIdx.z.
// 256 threads, 128x128 tile, 2 CTAs/SM (R13/R14-proven).
// ---------------------------------------------------------------------------
template <bool CONVERT_A, bool RELU>
__global__ __launch_bounds__(256, 2)
void mlp_hmma_kernel(const float* __restrict__ Af0,
                     const __half* __restrict__ Ag0,
                     const __half* __restrict__ Bh0,
                     const float* __restrict__ bias0,
                     __half* __restrict__ Oh0,
                     const float* __restrict__ Af1,
                     const __half* __restrict__ Ag1,
                     const __half* __restrict__ Bh1,
                     const float* __restrict__ bias1,
                     __half* __restrict__ Oh1,
                     int K) {
    const float*  Af   = blockIdx.z ? Af1   : Af0;
    const __half* Ag   = blockIdx.z ? Ag1   : Ag0;
    const __half* Bh   = blockIdx.z ? Bh1   : Bh0;
    const float*  bias = blockIdx.z ? bias1 : bias0;
    __half*       Oh   = blockIdx.z ? Oh1   : Oh0;

    const uint32_t sb = smem_u32(dsm);
    const int tid  = threadIdx.x;
    const int wid  = tid >> 5;
    const int lane = tid & 31;
    const int bm = blockIdx.x * 128;
    const int bn = blockIdx.y * 128;
    const int NCH = K / BKC;

    const int wm = (wid >> 2) * 64;
    const int wn = (wid & 3) * 32;

    float acc[4][4][4];
    #pragma unroll
    for (int mi = 0; mi < 4; ++mi)
        #pragma unroll
        for (int nf = 0; nf < 4; ++nf)
            #pragma unroll
            for (int r = 0; r < 4; ++r) acc[mi][nf][r] = 0.f;

    const int aRow = wm + (lane & 15);
    const int aSeg = (lane >> 4) << 4;
    const int bg   = lane >> 3;
    const int bRow = wn + ((bg >> 1) << 3) + (lane & 7);
    const int bSeg = (bg & 1) << 4;

    float4 areg[4];

    auto prefetch_B = [&](int c, int buf) {
        const int k0 = c * BKC;
        const uint32_t base = sb + buf * BUF_PB;
        #pragma unroll
        for (int i = 0; i < 2; ++i) {
            int u = tid + i * 256;
            int row = u >> 2, seg = u & 3;
            uint32_t dst = base + 1 * TILE_PB + row * ROWB + seg * 16;
            const __half* src = Bh + (size_t)(bn + row) * K + k0 + seg * 8;
            CP_ASYNC_16(dst, src);
        }
    };
    auto prefetch_A_f16 = [&](int c, int buf) {
        const int k0 = c * BKC;
        const uint32_t base = sb + buf * BUF_PB;
        #pragma unroll
        for (int i = 0; i < 2; ++i) {
            int u = tid + i * 256;
            int row = u >> 2, seg = u & 3;
            uint32_t dst = base + row * ROWB + seg * 16;
            const __half* src = Ag + (size_t)(bm + row) * K + k0 + seg * 8;
            CP_ASYNC_16(dst, src);
        }
    };
    auto ldg_A_f32 = [&](int c) {
        const int k0 = c * BKC;
        #pragma unroll
        for (int i = 0; i < 4; ++i) {
            int s = tid + i * 256;
            int row = s >> 3, seg = s & 7;
            areg[i] = *(const float4*)&Af[(size_t)(bm + row) * K + k0 + seg * 4];
        }
    };
    auto sts_A_cvt = [&](int buf) {
        const uint32_t base = sb + buf * BUF_PB;
        #pragma unroll
        for (int i = 0; i < 4; ++i) {
            int s = tid + i * 256;
            int row = s >> 3, seg = s & 7;
            uint32_t off = row * ROWB + seg * 8;
            float4 v = areg[i];
            __half2 h01 = __halves2half2(__float2half_rn(v.x), __float2half_rn(v.y));
            __half2 h23 = __halves2half2(__float2half_rn(v.z), __float2half_rn(v.w));
            uint32_t hu0 = *(uint32_t*)&h01, hu1 = *(uint32_t*)&h23;
            asm volatile("st.shared.v2.b32 [%0], {%1, %2};"
                         :: "r"(base + off), "r"(hu0), "r"(hu1) : "memory");
        }
    };

    if (CONVERT_A) {
        ldg_A_f32(0);
        prefetch_B(0, 0);
        CP_ASYNC_COMMIT();
    } else {
        prefetch_A_f16(0, 0);
        prefetch_B(0, 0);
        CP_ASYNC_COMMIT();
    }

    for (int c = 0; c < NCH; ++c) {
        const int buf = c & 1;
        if (CONVERT_A) {
            sts_A_cvt(buf);
            if (c + 1 < NCH) {
                prefetch_B(c + 1, buf ^ 1);
                CP_ASYNC_COMMIT();
                CP_ASYNC_WAIT_1();
            } else {
                CP_ASYNC_WAIT_0();
            }
            __syncthreads();
            if (c + 1 < NCH) ldg_A_f32(c + 1);
        } else {
            if (c + 1 < NCH) {
                prefetch_A_f16(c + 1, buf ^ 1);
                prefetch_B(c + 1, buf ^ 1);
                CP_ASYNC_COMMIT();
                CP_ASYNC_WAIT_1();
            } else {
                CP_ASYNC_WAIT_0();
            }
            __syncthreads();
        }

        const uint32_t tb  = sb + buf * BUF_PB;
        const uint32_t ahB = tb;
        const uint32_t bhB = tb + 1 * TILE_PB;

        #pragma unroll
        for (int ks = 0; ks < 2; ++ks) {
            const int kbyte = ks * 32;
            uint32_t ah[4][4], ph[4][2];
            #pragma unroll
            for (int mi = 0; mi < 4; ++mi) {
                uint32_t off = (uint32_t)(aRow + mi * 16) * ROWB + kbyte + aSeg;
                LDSM_X4(ah[mi], ahB + off);
            }
            #pragma unroll
            for (int ni = 0; ni < 2; ++ni) {
                uint32_t off = (uint32_t)(bRow + ni * 16) * ROWB + kbyte + bSeg;
                uint32_t r[4];
                LDSM_X4(r, bhB + off);
                ph[2 * ni][0] = r[0]; ph[2 * ni][1] = r[1];
                ph[2 * ni + 1][0] = r[2]; ph[2 * ni + 1][1] = r[3];
            }
            #pragma unroll
            for (int mi = 0; mi < 4; ++mi)
                #pragma unroll
                for (int nf = 0; nf < 4; ++nf)
                    mma_f16(acc[mi][nf], ah[mi], ph[nf]);
        }
        __syncthreads();
    }

    #pragma unroll
    for (int mi = 0; mi < 4; ++mi) {
        int r0 = bm + wm + mi * 16 + (lane >> 2);
        #pragma unroll
        for (int nf = 0; nf < 4; ++nf) {
            int cn = bn + wn + nf * 8 + 2 * (lane & 3);
            float b0 = bias[cn], b1 = bias[cn + 1];
            #pragma unroll
            for (int half_ = 0; half_ < 2; ++half_) {
                int r = r0 + half_ * 8;
                float o0 = acc[mi][nf][2 * half_ + 0] + b0;
                float o1 = acc[mi][nf][2 * half_ + 1] + b1;
                if (RELU) { o0 = fmaxf(o0, 0.f); o1 = fmaxf(o1, 0.f); }
                __half2 hh = __halves2half2(__float2half_rn(o0),
                                            __float2half_rn(o1));
                *(__half2*)&Oh[(size_t)r * DHD + cn] = hh;
            }
        }
    }
}

// ---------------------------------------------------------------------------
// Correlation v8: 64x64 warp tiles to cut smem crossbar traffic 1.5x.
//   128 threads (4 warps, 2x2 over 128x128 CTA tile), K-split x2 (288 CTAs =
//   2 CTAs/SM at 256 thr/SM -> 256-reg budget). BKC=64, double buffer.
//   128 B smem read per HMMA (vs 192 with 64x32 warp tiles).
// ---------------------------------------------------------------------------
#define BKC7     64
#define KHALF    (KCORR / 2)         // 16384
#define NCH7     (KHALF / BKC7)      // 256
#define ROW7     144                 // 128B data + 16 pad
#define TILE7    (128 * ROW7)        // 18432
#define BUF7     (2 * TILE7)         // A, P = 36864
#define CORR_SMEM (2 * BUF7)         // 73728 (x2 CTAs = 147456 <= 227K)

__device__ __forceinline__ void corr_prefetch8(
    uint32_t sb, int buf, int kglob, int bm, int bn, int lag,
    const __half* __restrict__ Ah, const __half* __restrict__ Ph, int tid)
{
    const int t  = kglob >> 8;                   // / 256
    const int d0 = kglob & 255;
    const int ts = (t + lag + TNT) & (TNT - 1);
    const int kb = ts * DHD + d0;

    const uint32_t base = sb + buf * BUF7;
    #pragma unroll
    for (int i = 0; i < 16; ++i) {
        int u    = tid + i * 128;                // 0..2047
        int tile = u >> 10;                      // 0..1
        int w    = u & 1023;
        int row  = w >> 3;                       // 0..127
        int seg  = w & 7;                        // 16B segment
        uint32_t dst = base + tile * TILE7 + row * ROW7 + seg * 16;
        const __half* src = (tile == 0)
            ? Ah + (size_t)(bm + row) * KCORR + kglob + seg * 8
            : Ph + (size_t)(bn + row) * KCORR + kb + seg * 8;
        CP_ASYNC_CG_16(dst, src);
    }
    CP_ASYNC_COMMIT();
}

__global__ __launch_bounds__(128, 2)
void corr_hmma_kernel(const __half* __restrict__ Ah,
                      const __half* __restrict__ Ph) {
    const uint32_t sb = smem_u32(dsm);
    const int tid  = threadIdx.x;
    const int wid  = tid >> 5;                   // 0..3
    const int lane = tid & 31;
    const int bm = blockIdx.x * 128;
    const int bn = blockIdx.y * 128;
    const int lagIdx = blockIdx.z >> 1;          // 0..8
    const int khalf  = blockIdx.z & 1;
    const int lag = lagIdx - MAXLAG;
    const int kbase = khalf * KHALF;

    const int wm = (wid >> 1) * 64;              // 0, 64
    const int wn = (wid & 1) * 64;               // 0, 64

    float acc[4][8][4];
    #pragma unroll
    for (int mi = 0; mi < 4; ++mi)
        #pragma unroll
        for (int nf = 0; nf < 8; ++nf)
            #pragma unroll
            for (int r = 0; r < 4; ++r) acc[mi][nf][r] = 0.f;

    const int aRow = wm + (lane & 15);
    const int aSeg = (lane >> 4) << 4;
    const int bg   = lane >> 3;
    const int bRow = wn + ((bg >> 1) << 3) + (lane & 7);
    const int bSeg = (bg & 1) << 4;

    corr_prefetch8(sb, 0, kbase, bm, bn, lag, Ah, Ph, tid);

    for (int c = 0; c < NCH7; ++c) {
        const int buf = c & 1;
        if (c + 1 < NCH7) {
            corr_prefetch8(sb, buf ^ 1, kbase + (c + 1) * BKC7,
                           bm, bn, lag, Ah, Ph, tid);
            CP_ASYNC_WAIT_1();
        } else {
            CP_ASYNC_WAIT_0();
        }
        __syncthreads();

        const uint32_t ahB = sb + buf * BUF7;
        const uint32_t phB = ahB + TILE7;

        #pragma unroll
        for (int ks = 0; ks < 4; ++ks) {
            const int kbyte = ks * 32;
            uint32_t ah[4][4], ph[8][2];
            #pragma unroll
            for (int mi = 0; mi < 4; ++mi) {
                uint32_t off = (uint32_t)(aRow + mi * 16) * ROW7 + kbyte + aSeg;
                LDSM_X4(ah[mi], ahB + off);
            }
            #pragma unroll
            for (int ni = 0; ni < 4; ++ni) {
                uint32_t off = (uint32_t)(bRow + ni * 16) * ROW7 + kbyte + bSeg;
                uint32_t r[4];
                LDSM_X4(r, phB + off);
                ph[2 * ni][0] = r[0]; ph[2 * ni][1] = r[1];
                ph[2 * ni + 1][0] = r[2]; ph[2 * ni + 1][1] = r[3];
            }
            #pragma unroll
            for (int mi = 0; mi < 4; ++mi)
                #pragma unroll
                for (int nf = 0; nf < 8; ++nf)
                    mma_f16(acc[mi][nf], ah[mi], ph[nf]);
        }
        __syncthreads();
    }

    // Epilogue: atomicAdd fp32 partial into per-lag buffer
    float* Sz = g_Sp + (size_t)lagIdx * QN * CN;
    #pragma unroll
    for (int mi = 0; mi < 4; ++mi) {
        int r0 = bm + wm + mi * 16 + (lane >> 2);
        #pragma unroll
        for (int nf = 0; nf < 8; ++nf) {
            int col = bn + wn + nf * 8 + 2 * (lane & 3);
            atomicAdd(&Sz[(size_t)r0 * CN + col],           acc[mi][nf][0]);
            atomicAdd(&Sz[(size_t)r0 * CN + col + 1],       acc[mi][nf][1]);
            atomicAdd(&Sz[(size_t)(r0 + 8) * CN + col],     acc[mi][nf][2]);
            atomicAdd(&Sz[(size_t)(r0 + 8) * CN + col + 1], acc[mi][nf][3]);
        }
    }
}

// ---------------------------------------------------------------------------
// Final max over lags
// ---------------------------------------------------------------------------
__global__ void maxlag_kernel(float* __restrict__ out) {
    int idx = blockIdx.x * blockDim.x + threadIdx.x;
    float m = g_Sp[idx];
    #pragma unroll
    for (int j = 1; j < NLAG; ++j)
        m = fmaxf(m, g_Sp[(size_t)j * QN * CN + idx]);
    out[idx] = m;
}

// ---------------------------------------------------------------------------
// Launch
// ---------------------------------------------------------------------------
extern "C" void kernel_launch(void* const* d_in, const int* in_sizes, int n_in,
                              void* d_out, int out_size) {
    const float* audio = (const float*)d_in[0];
    const float* video = (const float*)d_in[1];
    const float* a_w1  = (const float*)d_in[2];
    const float* a_b1  = (const float*)d_in[3];
    const float* a_w2  = (const float*)d_in[4];
    const float* a_b2  = (const float*)d_in[5];
    const float* v_w1  = (const float*)d_in[6];
    const float* v_b1  = (const float*)d_in[7];
    const float* v_w2  = (const float*)d_in[8];
    const float* v_b2  = (const float*)d_in[9];
    const float* W     = (const float*)d_in[10];
    float* out = (float*)d_out;

    float *gWc, *gbc;
    __half *gHha, *gHhv, *gAhf, *gPhf;
    __half *gW1ah, *gW1vh, *gW2ah, *gWcth;
    cudaGetSymbolAddress((void**)&gHha, g_Hha);
    cudaGetSymbolAddress((void**)&gHhv, g_Hhv);
    cudaGetSymbolAddress((void**)&gAhf, g_Ahf);
    cudaGetSymbolAddress((void**)&gPhf, g_Phf);
    cudaGetSymbolAddress((void**)&gWc, g_Wc);
    cudaGetSymbolAddress((void**)&gbc, g_bc);
    cudaGetSymbolAddress((void**)&gW1ah, g_W1ah);
    cudaGetSymbolAddress((void**)&gW1vh, g_W1vh);
    cudaGetSymbolAddress((void**)&gW2ah, g_W2ah);
    cudaGetSymbolAddress((void**)&gWcth, g_Wcth);

    cudaFuncSetAttribute(corr_hmma_kernel,
                         cudaFuncAttributeMaxDynamicSharedMemorySize, CORR_SMEM);
    cudaFuncSetAttribute(mlp_hmma_kernel<true, true>,
                         cudaFuncAttributeMaxDynamicSharedMemorySize, HMMA_SMEM);
    cudaFuncSetAttribute(mlp_hmma_kernel<false, false>,
                         cudaFuncAttributeMaxDynamicSharedMemorySize, HMMA_SMEM);

    // 0) prep: fold Wc, then one batched convert (+ g_Sp reset in same grid)
    prep_w_kernel<<<DHD, DHD>>>(v_w2, v_b2, W);
    convt_all_kernel<<<dim3(DHD, 5), 256>>>(
        a_w1, gW1ah, DIN,
        v_w1, gW1vh, DIN,
        a_w2, gW2ah, DHD,
        gWc,  gWcth, DHD);

    const dim3 mlp_grid(MROWS / 128, DHD / 128, 2);   // 512 x 2 x {audio,video}

    // 1) layer 1 for BOTH streams in one launch
    mlp_hmma_kernel<true, true><<<mlp_grid, 256, HMMA_SMEM>>>(
        audio, nullptr, gW1ah, a_b1, gHha,
        video, nullptr, gW1vh, v_b1, gHhv, DIN);

    // 2) layer 2 for BOTH streams in one launch
    mlp_hmma_kernel<false, false><<<mlp_grid, 256, HMMA_SMEM>>>(
        nullptr, gHha, gW2ah, a_b2, gAhf,
        nullptr, gHhv, gWcth, gbc, gPhf, DHD);

    // 3) per-lag correlation: 64x64 warp tiles, K-split x2, 288 CTAs
    corr_hmma_kernel<<<dim3(QN / 128, CN / 128, NLAG * 2), 128, CORR_SMEM>>>(
        gAhf, gPhf);

    // 4) max over lags
    maxlag_kernel<<<(QN * CN) / 256, 256>>>(out);
}

// round 16
// speedup vs baseline: 1.0501x; 1.0501x over previous
#include <cuda_runtime.h>
#include <cuda_fp16.h>
#include <cstdint>

// Problem dims (fixed by the reference)
#define QN   512
#define CN   512
#define TNT  128
#define DIN  512
#define DHD  256
#define KCORR (TNT * DHD)   // 32768
#define MAXLAG 4
#define NLAG  9             // lags -4..4
#define MROWS (QN * TNT)    // 65536

// ---------------------------------------------------------------------------
// Scratch (static device globals; no allocation allowed)
// ---------------------------------------------------------------------------
__device__ __half g_Hha[MROWS * DHD];   // audio hidden fp16
__device__ __half g_Hhv[MROWS * DHD];   // video hidden fp16
__device__ __half g_Ahf[MROWS * DHD];   // audio features fp16  [Q, T*DH]
__device__ __half g_Phf[MROWS * DHD];   // projected video fp16 [C, T*DH]
__device__ float g_Wc[DHD * DHD];       // folded v_w2 @ W (fp32)
__device__ float g_bc[DHD];             // folded v_b2 @ W
// pre-converted, pre-transposed weights: [N][K], K contiguous (fp16)
__device__ __half g_W1ah[DHD * DIN];
__device__ __half g_W1vh[DHD * DIN];
__device__ __half g_W2ah[DHD * DHD];
__device__ __half g_Wcth[DHD * DHD];
__device__ float g_Sp[NLAG * QN * CN];  // per-lag scores (atomicAdd partials)

// ---------------------------------------------------------------------------
// Portable PTX helpers (valid on compute_103 virtual target)
// ---------------------------------------------------------------------------
__device__ __forceinline__ uint32_t smem_u32(const void* p) {
    uint32_t a;
    asm("{ .reg .u64 t; cvta.to.shared.u64 t, %1; cvt.u32.u64 %0, t; }"
        : "=r"(a) : "l"(p));
    return a;
}

#define CP_ASYNC_16(dst, src) \
    asm volatile("cp.async.ca.shared.global [%0], [%1], 16;" \
        :: "r"(dst), "l"(src) : "memory")
#define CP_ASYNC_CG_16(dst, src) \
    asm volatile("cp.async.cg.shared.global [%0], [%1], 16;" \
        :: "r"(dst), "l"(src) : "memory")
#define CP_ASYNC_COMMIT() asm volatile("cp.async.commit_group;" ::: "memory")
#define CP_ASYNC_WAIT_1() asm volatile("cp.async.wait_group 1;" ::: "memory")
#define CP_ASYNC_WAIT_0() asm volatile("cp.async.wait_group 0;" ::: "memory")

#define LDSM_X4(r, addr) \
    asm volatile("ldmatrix.sync.aligned.m8n8.x4.shared.b16 {%0,%1,%2,%3}, [%4];" \
        : "=r"((r)[0]), "=r"((r)[1]), "=r"((r)[2]), "=r"((r)[3]) : "r"(addr))

__device__ __forceinline__ void mma_f16(float* c, const uint32_t* a,
                                        const uint32_t* b) {
    asm volatile(
        "mma.sync.aligned.m16n8k16.row.col.f32.f16.f16.f32 "
        "{%0,%1,%2,%3}, {%4,%5,%6,%7}, {%8,%9}, {%0,%1,%2,%3};"
        : "+f"(c[0]), "+f"(c[1]), "+f"(c[2]), "+f"(c[3])
        : "r"(a[0]), "r"(a[1]), "r"(a[2]), "r"(a[3]), "r"(b[0]), "r"(b[1]));
}

// ---------------------------------------------------------------------------
// Prep: fold v_w2 @ W -> g_Wc, g_bc
// ---------------------------------------------------------------------------
__global__ void prep_w_kernel(const float* __restrict__ v_w2,
                              const float* __restrict__ v_b2,
                              const float* __restrict__ W) {
    int i = blockIdx.x;
    int j = threadIdx.x;
    float acc = 0.f;
    #pragma unroll 8
    for (int k = 0; k < DHD; ++k)
        acc += v_w2[i * DHD + k] * W[k * DHD + j];
    g_Wc[i * DHD + j] = acc;
    if (i == 0) {
        float accb = 0.f;
        #pragma unroll 8
        for (int k = 0; k < DHD; ++k)
            accb += v_b2[k] * W[k * DHD + j];
        g_bc[j] = accb;
    }
}

// Prep: batched transpose+convert fp32 [K,256] -> fp16 [256][K] for 4 arrays,
// plus reset of g_Sp (blockIdx.y == 4).
__global__ void convt_all_kernel(const float* __restrict__ s0, __half* d0, int K0,
                                 const float* __restrict__ s1, __half* d1, int K1,
                                 const float* __restrict__ s2, __half* d2, int K2,
                                 const float* __restrict__ s3, __half* d3, int K3) {
    int which = blockIdx.y;
    if (which == 4) {   // reset g_Sp to 0
        int idx = blockIdx.x * blockDim.x + threadIdx.x;
        for (; idx < NLAG * QN * CN; idx += gridDim.x * blockDim.x)
            g_Sp[idx] = 0.f;
        return;
    }
    const float* in; __half* oh; int K;
    if (which == 0)      { in = s0; oh = d0; K = K0; }
    else if (which == 1) { in = s1; oh = d1; K = K1; }
    else if (which == 2) { in = s2; oh = d2; K = K2; }
    else                 { in = s3; oh = d3; K = K3; }
    int n = blockIdx.x;
    for (int k = threadIdx.x; k < K; k += blockDim.x)
        oh[(size_t)n * K + k] = __float2half_rn(in[(size_t)k * DHD + n]);
}

// ---------------------------------------------------------------------------
// MLP tiling constants (2 tiles: A, B)
// ---------------------------------------------------------------------------
#define BKC     32                  // K elems per chunk (MLP)
#define ROWB    80                  // padded row stride bytes (64 data + 16)
#define TILE_PB (128 * ROWB)        // 10240
#define BUF_PB  (2 * TILE_PB)       // A, B = 20480
#define HMMA_SMEM (2 * BUF_PB)      // 40960

extern __shared__ char dsm[];

// ---------------------------------------------------------------------------
// MLP layer 1 on HMMA (fp32 in, fp16 out), batched audio/video via z.
// 256 threads, 128x128 tile, 64x32 warp tiles, 2 CTAs/SM (R13/R14-proven).
// ---------------------------------------------------------------------------
__global__ __launch_bounds__(256, 2)
void mlp1_hmma_kernel(const float* __restrict__ Af0,
                      const __half* __restrict__ Bh0,
                      const float* __restrict__ bias0,
                      __half* __restrict__ Oh0,
                      const float* __restrict__ Af1,
                      const __half* __restrict__ Bh1,
                      const float* __restrict__ bias1,
                      __half* __restrict__ Oh1,
                      int K) {
    const float*  Af   = blockIdx.z ? Af1   : Af0;
    const __half* Bh   = blockIdx.z ? Bh1   : Bh0;
    const float*  bias = blockIdx.z ? bias1 : bias0;
    __half*       Oh   = blockIdx.z ? Oh1   : Oh0;

    const uint32_t sb = smem_u32(dsm);
    const int tid  = threadIdx.x;
    const int wid  = tid >> 5;
    const int lane = tid & 31;
    const int bm = blockIdx.x * 128;
    const int bn = blockIdx.y * 128;
    const int NCH = K / BKC;

    const int wm = (wid >> 2) * 64;
    const int wn = (wid & 3) * 32;

    float acc[4][4][4];
    #pragma unroll
    for (int mi = 0; mi < 4; ++mi)
        #pragma unroll
        for (int nf = 0; nf < 4; ++nf)
            #pragma unroll
            for (int r = 0; r < 4; ++r) acc[mi][nf][r] = 0.f;

    const int aRow = wm + (lane & 15);
    const int aSeg = (lane >> 4) << 4;
    const int bg   = lane >> 3;
    const int bRow = wn + ((bg >> 1) << 3) + (lane & 7);
    const int bSeg = (bg & 1) << 4;

    float4 areg[4];

    auto prefetch_B = [&](int c, int buf) {
        const int k0 = c * BKC;
        const uint32_t base = sb + buf * BUF_PB;
        #pragma unroll
        for (int i = 0; i < 2; ++i) {
            int u = tid + i * 256;
            int row = u >> 2, seg = u & 3;
            uint32_t dst = base + 1 * TILE_PB + row * ROWB + seg * 16;
            const __half* src = Bh + (size_t)(bn + row) * K + k0 + seg * 8;
            CP_ASYNC_16(dst, src);
        }
    };
    auto ldg_A_f32 = [&](int c) {
        const int k0 = c * BKC;
        #pragma unroll
        for (int i = 0; i < 4; ++i) {
            int s = tid + i * 256;
            int row = s >> 3, seg = s & 7;
            areg[i] = *(const float4*)&Af[(size_t)(bm + row) * K + k0 + seg * 4];
        }
    };
    auto sts_A_cvt = [&](int buf) {
        const uint32_t base = sb + buf * BUF_PB;
        #pragma unroll
        for (int i = 0; i < 4; ++i) {
            int s = tid + i * 256;
            int row = s >> 3, seg = s & 7;
            uint32_t off = row * ROWB + seg * 8;
            float4 v = areg[i];
            __half2 h01 = __halves2half2(__float2half_rn(v.x), __float2half_rn(v.y));
            __half2 h23 = __halves2half2(__float2half_rn(v.z), __float2half_rn(v.w));
            uint32_t hu0 = *(uint32_t*)&h01, hu1 = *(uint32_t*)&h23;
            asm volatile("st.shared.v2.b32 [%0], {%1, %2};"
                         :: "r"(base + off), "r"(hu0), "r"(hu1) : "memory");
        }
    };

    ldg_A_f32(0);
    prefetch_B(0, 0);
    CP_ASYNC_COMMIT();

    for (int c = 0; c < NCH; ++c) {
        const int buf = c & 1;
        sts_A_cvt(buf);
        if (c + 1 < NCH) {
            prefetch_B(c + 1, buf ^ 1);
            CP_ASYNC_COMMIT();
            CP_ASYNC_WAIT_1();
        } else {
            CP_ASYNC_WAIT_0();
        }
        __syncthreads();
        if (c + 1 < NCH) ldg_A_f32(c + 1);

        const uint32_t tb  = sb + buf * BUF_PB;
        const uint32_t ahB = tb;
        const uint32_t bhB = tb + 1 * TILE_PB;

        #pragma unroll
        for (int ks = 0; ks < 2; ++ks) {
            const int kbyte = ks * 32;
            uint32_t ah[4][4], ph[4][2];
            #pragma unroll
            for (int mi = 0; mi < 4; ++mi) {
                uint32_t off = (uint32_t)(aRow + mi * 16) * ROWB + kbyte + aSeg;
                LDSM_X4(ah[mi], ahB + off);
            }
            #pragma unroll
            for (int ni = 0; ni < 2; ++ni) {
                uint32_t off = (uint32_t)(bRow + ni * 16) * ROWB + kbyte + bSeg;
                uint32_t r[4];
                LDSM_X4(r, bhB + off);
                ph[2 * ni][0] = r[0]; ph[2 * ni][1] = r[1];
                ph[2 * ni + 1][0] = r[2]; ph[2 * ni + 1][1] = r[3];
            }
            #pragma unroll
            for (int mi = 0; mi < 4; ++mi)
                #pragma unroll
                for (int nf = 0; nf < 4; ++nf)
                    mma_f16(acc[mi][nf], ah[mi], ph[nf]);
        }
        __syncthreads();
    }

    #pragma unroll
    for (int mi = 0; mi < 4; ++mi) {
        int r0 = bm + wm + mi * 16 + (lane >> 2);
        #pragma unroll
        for (int nf = 0; nf < 4; ++nf) {
            int cn = bn + wn + nf * 8 + 2 * (lane & 3);
            float b0 = bias[cn], b1 = bias[cn + 1];
            #pragma unroll
            for (int half_ = 0; half_ < 2; ++half_) {
                int r = r0 + half_ * 8;
                float o0 = fmaxf(acc[mi][nf][2 * half_ + 0] + b0, 0.f);
                float o1 = fmaxf(acc[mi][nf][2 * half_ + 1] + b1, 0.f);
                __half2 hh = __halves2half2(__float2half_rn(o0),
                                            __float2half_rn(o1));
                *(__half2*)&Oh[(size_t)r * DHD + cn] = hh;
            }
        }
    }
}

// ---------------------------------------------------------------------------
// MLP layer 2 on HMMA: crossbar-relieved. fp16 in/out, no relu.
//   128 threads, 4 warps as 2x2 of 64x64 tiles over 128x128; 3 CTAs/SM
//   (launch_bounds(128,3) -> reg cap 170; 3 warps/SMSP avoids R15's 2-warp
//   bubble trap). 128 B smem read per HMMA (vs 192).
// ---------------------------------------------------------------------------
__global__ __launch_bounds__(128, 3)
void mlp2_hmma_kernel(const __half* __restrict__ Ag0,
                      const __half* __restrict__ Bh0,
                      const float* __restrict__ bias0,
                      __half* __restrict__ Oh0,
                      const __half* __restrict__ Ag1,
                      const __half* __restrict__ Bh1,
                      const float* __restrict__ bias1,
                      __half* __restrict__ Oh1,
                      int K) {
    const __half* Ag   = blockIdx.z ? Ag1   : Ag0;
    const __half* Bh   = blockIdx.z ? Bh1   : Bh0;
    const float*  bias = blockIdx.z ? bias1 : bias0;
    __half*       Oh   = blockIdx.z ? Oh1   : Oh0;

    const uint32_t sb = smem_u32(dsm);
    const int tid  = threadIdx.x;
    const int wid  = tid >> 5;                   // 0..3
    const int lane = tid & 31;
    const int bm = blockIdx.x * 128;
    const int bn = blockIdx.y * 128;
    const int NCH = K / BKC;

    const int wm = (wid >> 1) * 64;              // 0, 64
    const int wn = (wid & 1) * 64;               // 0, 64

    float acc[4][8][4];
    #pragma unroll
    for (int mi = 0; mi < 4; ++mi)
        #pragma unroll
        for (int nf = 0; nf < 8; ++nf)
            #pragma unroll
            for (int r = 0; r < 4; ++r) acc[mi][nf][r] = 0.f;

    const int aRow = wm + (lane & 15);
    const int aSeg = (lane >> 4) << 4;
    const int bg   = lane >> 3;
    const int bRow = wn + ((bg >> 1) << 3) + (lane & 7);
    const int bSeg = (bg & 1) << 4;

    auto prefetch = [&](int c, int buf) {
        const int k0 = c * BKC;
        const uint32_t base = sb + buf * BUF_PB;
        #pragma unroll
        for (int i = 0; i < 8; ++i) {
            int u = tid + i * 128;               // 0..1023
            int tile = u >> 9;                   // 0: A, 1: B
            int w = u & 511;
            int row = w >> 2, seg = w & 3;
            uint32_t dst = base + tile * TILE_PB + row * ROWB + seg * 16;
            const __half* src = (tile == 0 ? Ag : Bh) +
                (size_t)((tile == 0 ? bm : bn) + row) * K + k0 + seg * 8;
            CP_ASYNC_16(dst, src);
        }
        CP_ASYNC_COMMIT();
    };

    prefetch(0, 0);

    for (int c = 0; c < NCH; ++c) {
        const int buf = c & 1;
        if (c + 1 < NCH) {
            prefetch(c + 1, buf ^ 1);
            CP_ASYNC_WAIT_1();
        } else {
            CP_ASYNC_WAIT_0();
        }
        __syncthreads();

        const uint32_t ahB = sb + buf * BUF_PB;
        const uint32_t bhB = ahB + TILE_PB;

        #pragma unroll
        for (int ks = 0; ks < 2; ++ks) {
            const int kbyte = ks * 32;
            uint32_t ah[4][4], ph[8][2];
            #pragma unroll
            for (int mi = 0; mi < 4; ++mi) {
                uint32_t off = (uint32_t)(aRow + mi * 16) * ROWB + kbyte + aSeg;
                LDSM_X4(ah[mi], ahB + off);
            }
            #pragma unroll
            for (int ni = 0; ni < 4; ++ni) {
                uint32_t off = (uint32_t)(bRow + ni * 16) * ROWB + kbyte + bSeg;
                uint32_t r[4];
                LDSM_X4(r, bhB + off);
                ph[2 * ni][0] = r[0]; ph[2 * ni][1] = r[1];
                ph[2 * ni + 1][0] = r[2]; ph[2 * ni + 1][1] = r[3];
            }
            #pragma unroll
            for (int mi = 0; mi < 4; ++mi)
                #pragma unroll
                for (int nf = 0; nf < 8; ++nf)
                    mma_f16(acc[mi][nf], ah[mi], ph[nf]);
        }
        __syncthreads();
    }

    #pragma unroll
    for (int mi = 0; mi < 4; ++mi) {
        int r0 = bm + wm + mi * 16 + (lane >> 2);
        #pragma unroll
        for (int nf = 0; nf < 8; ++nf) {
            int cn = bn + wn + nf * 8 + 2 * (lane & 3);
            float b0 = bias[cn], b1 = bias[cn + 1];
            #pragma unroll
            for (int half_ = 0; half_ < 2; ++half_) {
                int r = r0 + half_ * 8;
                float o0 = acc[mi][nf][2 * half_ + 0] + b0;
                float o1 = acc[mi][nf][2 * half_ + 1] + b1;
                __half2 hh = __halves2half2(__float2half_rn(o0),
                                            __float2half_rn(o1));
                *(__half2*)&Oh[(size_t)r * DHD + cn] = hh;
            }
        }
    }
}

// ---------------------------------------------------------------------------
// Correlation v7 (EXACT R14, proven best): K-split x2 -> 288 CTAs = 2/SM,
//   128x128 tile, 256 threads, 64x32 warp tiles, BKC=64, double buffer,
//   fp32 atomicAdd partials.
// ---------------------------------------------------------------------------
#define BKC7     64
#define KHALF    (KCORR / 2)         // 16384
#define NCH7     (KHALF / BKC7)      // 256
#define ROW7     144                 // 128B data + 16 pad
#define TILE7    (128 * ROW7)        // 18432
#define BUF7     (2 * TILE7)         // A, P = 36864
#define CORR_SMEM (2 * BUF7)         // 73728

__device__ __forceinline__ void corr_prefetch7(
    uint32_t sb, int buf, int kglob, int bm, int bn, int lag,
    const __half* __restrict__ Ah, const __half* __restrict__ Ph, int tid)
{
    const int t  = kglob >> 8;                   // / 256
    const int d0 = kglob & 255;
    const int ts = (t + lag + TNT) & (TNT - 1);
    const int kb = ts * DHD + d0;

    const uint32_t base = sb + buf * BUF7;
    #pragma unroll
    for (int i = 0; i < 8; ++i) {
        int u    = tid + i * 256;                // 0..2047
        int tile = u >> 10;                      // 0..1
        int w    = u & 1023;
        int row  = w >> 3;                       // 0..127
        int seg  = w & 7;                        // 16B segment
        uint32_t dst = base + tile * TILE7 + row * ROW7 + seg * 16;
        const __half* src = (tile == 0)
            ? Ah + (size_t)(bm + row) * KCORR + kglob + seg * 8
            : Ph + (size_t)(bn + row) * KCORR + kb + seg * 8;
        CP_ASYNC_CG_16(dst, src);
    }
    CP_ASYNC_COMMIT();
}

__global__ __launch_bounds__(256, 2)
void corr_hmma_kernel(const __half* __restrict__ Ah,
                      const __half* __restrict__ Ph) {
    const uint32_t sb = smem_u32(dsm);
    const int tid  = threadIdx.x;
    const int wid  = tid >> 5;
    const int lane = tid & 31;
    const int bm = blockIdx.x * 128;
    const int bn = blockIdx.y * 128;
    const int lagIdx = blockIdx.z >> 1;          // 0..8
    const int khalf  = blockIdx.z & 1;
    const int lag = lagIdx - MAXLAG;
    const int kbase = khalf * KHALF;

    const int wm = (wid >> 2) * 64;              // 0, 64
    const int wn = (wid & 3) * 32;               // 0,32,64,96

    float acc[4][4][4];
    #pragma unroll
    for (int mi = 0; mi < 4; ++mi)
        #pragma unroll
        for (int nf = 0; nf < 4; ++nf)
            #pragma unroll
            for (int r = 0; r < 4; ++r) acc[mi][nf][r] = 0.f;

    const int aRow = wm + (lane & 15);
    const int aSeg = (lane >> 4) << 4;
    const int bg   = lane >> 3;
    const int bRow = wn + ((bg >> 1) << 3) + (lane & 7);
    const int bSeg = (bg & 1) << 4;

    corr_prefetch7(sb, 0, kbase, bm, bn, lag, Ah, Ph, tid);

    for (int c = 0; c < NCH7; ++c) {
        const int buf = c & 1;
        if (c + 1 < NCH7) {
            corr_prefetch7(sb, buf ^ 1, kbase + (c + 1) * BKC7,
                           bm, bn, lag, Ah, Ph, tid);
            CP_ASYNC_WAIT_1();
        } else {
            CP_ASYNC_WAIT_0();
        }
        __syncthreads();

        const uint32_t ahB = sb + buf * BUF7;
        const uint32_t phB = ahB + TILE7;

        #pragma unroll
        for (int ks = 0; ks < 4; ++ks) {
            const int kbyte = ks * 32;
            uint32_t ah[4][4], ph[4][2];
            #pragma unroll
            for (int mi = 0; mi < 4; ++mi) {
                uint32_t off = (uint32_t)(aRow + mi * 16) * ROW7 + kbyte + aSeg;
                LDSM_X4(ah[mi], ahB + off);
            }
            #pragma unroll
            for (int ni = 0; ni < 2; ++ni) {
                uint32_t off = (uint32_t)(bRow + ni * 16) * ROW7 + kbyte + bSeg;
                uint32_t r[4];
                LDSM_X4(r, phB + off);
                ph[2 * ni][0] = r[0]; ph[2 * ni][1] = r[1];
                ph[2 * ni + 1][0] = r[2]; ph[2 * ni + 1][1] = r[3];
            }
            #pragma unroll
            for (int mi = 0; mi < 4; ++mi)
                #pragma unroll
                for (int nf = 0; nf < 4; ++nf)
                    mma_f16(acc[mi][nf], ah[mi], ph[nf]);
        }
        __syncthreads();
    }

    float* Sz = g_Sp + (size_t)lagIdx * QN * CN;
    #pragma unroll
    for (int mi = 0; mi < 4; ++mi) {
        int r0 = bm + wm + mi * 16 + (lane >> 2);
        #pragma unroll
        for (int nf = 0; nf < 4; ++nf) {
            int col = bn + wn + nf * 8 + 2 * (lane & 3);
            atomicAdd(&Sz[(size_t)r0 * CN + col],           acc[mi][nf][0]);
            atomicAdd(&Sz[(size_t)r0 * CN + col + 1],       acc[mi][nf][1]);
            atomicAdd(&Sz[(size_t)(r0 + 8) * CN + col],     acc[mi][nf][2]);
            atomicAdd(&Sz[(size_t)(r0 + 8) * CN + col + 1], acc[mi][nf][3]);
        }
    }
}

// ---------------------------------------------------------------------------
// Final max over lags
// ---------------------------------------------------------------------------
__global__ void maxlag_kernel(float* __restrict__ out) {
    int idx = blockIdx.x * blockDim.x + threadIdx.x;
    float m = g_Sp[idx];
    #pragma unroll
    for (int j = 1; j < NLAG; ++j)
        m = fmaxf(m, g_Sp[(size_t)j * QN * CN + idx]);
    out[idx] = m;
}

// ---------------------------------------------------------------------------
// Launch
// ---------------------------------------------------------------------------
extern "C" void kernel_launch(void* const* d_in, const int* in_sizes, int n_in,
                              void* d_out, int out_size) {
    const float* audio = (const float*)d_in[0];
    const float* video = (const float*)d_in[1];
    const float* a_w1  = (const float*)d_in[2];
    const float* a_b1  = (const float*)d_in[3];
    const float* a_w2  = (const float*)d_in[4];
    const float* a_b2  = (const float*)d_in[5];
    const float* v_w1  = (const float*)d_in[6];
    const float* v_b1  = (const float*)d_in[7];
    const float* v_w2  = (const float*)d_in[8];
    const float* v_b2  = (const float*)d_in[9];
    const float* W     = (const float*)d_in[10];
    float* out = (float*)d_out;

    float *gWc, *gbc;
    __half *gHha, *gHhv, *gAhf, *gPhf;
    __half *gW1ah, *gW1vh, *gW2ah, *gWcth;
    cudaGetSymbolAddress((void**)&gHha, g_Hha);
    cudaGetSymbolAddress((void**)&gHhv, g_Hhv);
    cudaGetSymbolAddress((void**)&gAhf, g_Ahf);
    cudaGetSymbolAddress((void**)&gPhf, g_Phf);
    cudaGetSymbolAddress((void**)&gWc, g_Wc);
    cudaGetSymbolAddress((void**)&gbc, g_bc);
    cudaGetSymbolAddress((void**)&gW1ah, g_W1ah);
    cudaGetSymbolAddress((void**)&gW1vh, g_W1vh);
    cudaGetSymbolAddress((void**)&gW2ah, g_W2ah);
    cudaGetSymbolAddress((void**)&gWcth, g_Wcth);

    cudaFuncSetAttribute(corr_hmma_kernel,
                         cudaFuncAttributeMaxDynamicSharedMemorySize, CORR_SMEM);
    cudaFuncSetAttribute(mlp1_hmma_kernel,
                         cudaFuncAttributeMaxDynamicSharedMemorySize, HMMA_SMEM);
    cudaFuncSetAttribute(mlp2_hmma_kernel,
                         cudaFuncAttributeMaxDynamicSharedMemorySize, HMMA_SMEM);

    // 0) prep: fold Wc, then one batched convert (+ g_Sp reset in same grid)
    prep_w_kernel<<<DHD, DHD>>>(v_w2, v_b2, W);
    convt_all_kernel<<<dim3(DHD, 5), 256>>>(
        a_w1, gW1ah, DIN,
        v_w1, gW1vh, DIN,
        a_w2, gW2ah, DHD,
        gWc,  gWcth, DHD);

    const dim3 mlp_grid(MROWS / 128, DHD / 128, 2);   // 512 x 2 x {audio,video}

    // 1) layer 1 for BOTH streams (256 thr, 2 CTAs/SM — proven)
    mlp1_hmma_kernel<<<mlp_grid, 256, HMMA_SMEM>>>(
        audio, gW1ah, a_b1, gHha,
        video, gW1vh, v_b1, gHhv, DIN);

    // 2) layer 2 for BOTH streams (128 thr, 64x64 warp tiles, 3 CTAs/SM)
    mlp2_hmma_kernel<<<mlp_grid, 128, HMMA_SMEM>>>(
        gHha, gW2ah, a_b2, gAhf,
        gHhv, gWcth, gbc, gPhf, DHD);

    // 3) per-lag correlation: EXACT R14 config (best known)
    corr_hmma_kernel<<<dim3(QN / 128, CN / 128, NLAG * 2), 256, CORR_SMEM>>>(
        gAhf, gPhf);

    // 4) max over lags
    maxlag_kernel<<<(QN * CN) / 256, 256>>>(out);
}